// round 10
// baseline (speedup 1.0000x reference)
#include <cuda_runtime.h>
#include <cuda_bf16.h>
#include <cstdint>
#include <cstddef>

#define Msz 4096
#define Ksz 4096
#define Nsz 4096
#define TKC 64
#define NCHUNK (Ksz / TKC)   // 64
#define TM 256
#define TN 128
#define NTILES ((Msz / TM) * (Nsz / TN))   // 512
#define GRIDP 148                          // 1 CTA/SM, persistent

// Scratch (static device globals: allocation-free at runtime)
__device__ __nv_bfloat16 g_Xb[(size_t)Msz * Ksz];   // x as bf16, [M,K] row-major
__device__ __nv_bfloat16 g_Yt[(size_t)Nsz * Ksz];   // y^T as bf16, [N,K] row-major
__device__ float g_R[Msz];                          // rowsum of x
__device__ float g_C[Nsz];                          // colsum of y
__device__ int g_tile_ctr;                          // persistent-scheduler counter

__device__ __forceinline__ uint32_t smem_u32(const void* p) {
    uint32_t a;
    asm("{ .reg .u64 t; cvta.to.shared.u64 t, %1; cvt.u32.u64 %0, t; }" : "=r"(a) : "l"(p));
    return a;
}

#define SWZ(off) ((off) ^ (((off) >> 3) & 0x70))

// ---------------- Prep kernels ----------------
__global__ void zero_c_kernel() {
    int i = blockIdx.x * blockDim.x + threadIdx.x;
    if (i < Nsz) g_C[i] = 0.0f;
    if (i == 0) g_tile_ctr = 0;   // reset scheduler every launch (determinism)
}

// One block per row of x: fp32 -> bf16 convert + rowsum
__global__ void prep_x_kernel(const float* __restrict__ x) {
    int m = blockIdx.x;
    const float4* xr = (const float4*)(x + (size_t)m * Ksz);
    uint2* dst = (uint2*)(g_Xb + (size_t)m * Ksz);
    float sum = 0.0f;
    for (int i = threadIdx.x; i < Ksz / 4; i += 256) {
        float4 v = xr[i];
        sum += (v.x + v.y) + (v.z + v.w);
        __nv_bfloat162 lo = __floats2bfloat162_rn(v.x, v.y);
        __nv_bfloat162 hi = __floats2bfloat162_rn(v.z, v.w);
        uint2 u;
        u.x = *reinterpret_cast<uint32_t*>(&lo);
        u.y = *reinterpret_cast<uint32_t*>(&hi);
        dst[i] = u;
    }
    #pragma unroll
    for (int o = 16; o; o >>= 1) sum += __shfl_xor_sync(0xFFFFFFFFu, sum, o);
    __shared__ float ws[8];
    if ((threadIdx.x & 31) == 0) ws[threadIdx.x >> 5] = sum;
    __syncthreads();
    if (threadIdx.x == 0) {
        float t = 0.0f;
        #pragma unroll
        for (int w = 0; w < 8; w++) t += ws[w];
        g_R[m] = t;
    }
}

// 32x32 tile transpose of y into Yt (bf16) + colsum via atomicAdd (partials exact ints)
__global__ void prep_y_kernel(const float* __restrict__ y) {
    __shared__ float tile[32][33];
    int n0 = blockIdx.x * 32, k0 = blockIdx.y * 32;
    int tx = threadIdx.x, ty = threadIdx.y;  // 32 x 8
    #pragma unroll
    for (int r = 0; r < 4; r++)
        tile[ty + r * 8][tx] = y[(size_t)(k0 + ty + r * 8) * Nsz + n0 + tx];
    __syncthreads();
    #pragma unroll
    for (int r = 0; r < 4; r++) {
        int row = ty + r * 8;
        g_Yt[(size_t)(n0 + row) * Ksz + k0 + tx] = __float2bfloat16(tile[tx][row]);
    }
    if (ty == 0) {
        float s = 0.0f;
        #pragma unroll
        for (int i = 0; i < 32; i++) s += tile[i][tx];
        atomicAdd(&g_C[n0 + tx], s);
    }
}

// ---------------- GEMM kernel: 256x128 CTA tile, warp 64x64, 4-stage, persistent ----------------
// Stage layout: A [0,32K) 256 rows x 128B swizzled; B [32K,48K) 128 rows x 128B.
#define ASTB 32768
#define BSTB 16384
#define STAGEBYTES (ASTB + BSTB)           // 48 KB
#define NSTAGE 4
#define SMEM_TOTAL (NSTAGE * STAGEBYTES + 128)   // 196736

__device__ __forceinline__ void load_chunk(uint32_t stage_base, int tid,
                                           int m0, int n0, int k0) {
    const char* xb = (const char*)g_Xb;
    const char* yb = (const char*)g_Yt;
    // A: 256 rows x 64 bf16
    #pragma unroll
    for (int e = 0; e < 8; e++) {
        int idx = tid + e * 256;
        int row = idx >> 3;      // 0..255
        int grp = idx & 7;
        uint32_t soff = SWZ((uint32_t)(row * 128 + grp * 16));
        size_t ea = ((size_t)(m0 + row) * Ksz + (size_t)(k0 + grp * 8)) * 2;
        asm volatile("cp.async.cg.shared.global [%0], [%1], 16;"
                     :: "r"(stage_base + soff), "l"(xb + ea) : "memory");
    }
    // B: 128 rows x 64 bf16
    #pragma unroll
    for (int e = 0; e < 4; e++) {
        int idx = tid + e * 256;
        int row = idx >> 3;      // 0..127
        int grp = idx & 7;
        uint32_t soff = SWZ((uint32_t)(row * 128 + grp * 16));
        size_t eb = ((size_t)(n0 + row) * Ksz + (size_t)(k0 + grp * 8)) * 2;
        asm volatile("cp.async.cg.shared.global [%0], [%1], 16;"
                     :: "r"(stage_base + ASTB + soff), "l"(yb + eb) : "memory");
    }
    asm volatile("cp.async.commit_group;" ::: "memory");
}

__device__ __forceinline__ void load_frags(uint32_t abase, uint32_t bbase, int ks,
                                           int a_row_lo, int a_kg_off,
                                           int b_row_lo, int b_kg_off,
                                           uint32_t afr[4][4], uint32_t bfr[4][4]) {
    #pragma unroll
    for (int mi = 0; mi < 4; mi++) {
        int row = a_row_lo + mi * 16;
        int kg = ks * 2 + a_kg_off;
        uint32_t addr = abase + SWZ((uint32_t)(row * 128 + kg * 16));
        asm volatile("ldmatrix.sync.aligned.m8n8.x4.shared.b16 {%0,%1,%2,%3}, [%4];"
                     : "=r"(afr[mi][0]), "=r"(afr[mi][1]),
                       "=r"(afr[mi][2]), "=r"(afr[mi][3])
                     : "r"(addr));
    }
    #pragma unroll
    for (int nj4 = 0; nj4 < 4; nj4++) {
        int row = b_row_lo + nj4 * 16;
        int kg = ks * 2 + b_kg_off;
        uint32_t addr = bbase + SWZ((uint32_t)(row * 128 + kg * 16));
        asm volatile("ldmatrix.sync.aligned.m8n8.x4.shared.b16 {%0,%1,%2,%3}, [%4];"
                     : "=r"(bfr[nj4][0]), "=r"(bfr[nj4][1]),
                       "=r"(bfr[nj4][2]), "=r"(bfr[nj4][3])
                     : "r"(addr));
    }
}

__global__ void __launch_bounds__(256, 1) gemm_kernel(float* __restrict__ out) {
    extern __shared__ char smem[];
    uint32_t sb = smem_u32(smem);
    int* s_tile = (int*)(smem + NSTAGE * STAGEBYTES);
    int tid = threadIdx.x;
    int lane = tid & 31;
    int wid = tid >> 5;
    int wm = (wid >> 1) * 64;   // 4 warps in M (tile 256)
    int wn = (wid & 1) * 64;    // 2 warps in N (tile 128)

    // ldmatrix address components (layout verified in round 2)
    int a_row_lo = wm + (lane & 15);                  // + mi*16
    int a_kg_off = (lane >> 4);                       // + ks*2
    int b_row_lo = wn + ((lane >> 4) << 3) + (lane & 7);   // + nj4*16
    int b_kg_off = ((lane >> 3) & 1);                      // + ks*2

    for (;;) {
        if (tid == 0) *s_tile = atomicAdd(&g_tile_ctr, 1);
        __syncthreads();
        int t = *s_tile;
        if (t >= NTILES) break;
        int m0 = (t >> 5) * TM;   // 32 n-tiles per m-strip: consecutive t share A strip
        int n0 = (t & 31) * TN;

        float acc[4][8][4];
        #pragma unroll
        for (int i = 0; i < 4; i++)
            #pragma unroll
            for (int j = 0; j < 8; j++)
                #pragma unroll
                for (int q = 0; q < 4; q++) acc[i][j][q] = 0.0f;

        // Prologue: prefetch chunks 0,1,2
        load_chunk(sb + 0 * STAGEBYTES, tid, m0, n0, 0);
        load_chunk(sb + 1 * STAGEBYTES, tid, m0, n0, TKC);
        load_chunk(sb + 2 * STAGEBYTES, tid, m0, n0, 2 * TKC);

        int stage = 0;
        for (int c = 0; c < NCHUNK; c++) {
            if (c + 2 < NCHUNK) {
                asm volatile("cp.async.wait_group 2;" ::: "memory");
            } else {
                asm volatile("cp.async.wait_group 0;" ::: "memory");
            }
            __syncthreads();   // chunk c visible; prior iteration's reads sealed

            if (c + 3 < NCHUNK) {
                int ls = stage + 3;
                if (ls >= NSTAGE) ls -= NSTAGE;
                load_chunk(sb + (uint32_t)ls * STAGEBYTES, tid, m0, n0, (c + 3) * TKC);
            }

            uint32_t abase = sb + (uint32_t)stage * STAGEBYTES;
            uint32_t bbase = abase + ASTB;

            // Double-buffered fragments across ks steps
            uint32_t afr[2][4][4], bfr[2][4][4];
            load_frags(abase, bbase, 0, a_row_lo, a_kg_off, b_row_lo, b_kg_off,
                       afr[0], bfr[0]);
            #pragma unroll
            for (int ks = 0; ks < 4; ks++) {
                int cur = ks & 1;
                if (ks < 3)
                    load_frags(abase, bbase, ks + 1, a_row_lo, a_kg_off,
                               b_row_lo, b_kg_off, afr[cur ^ 1], bfr[cur ^ 1]);
                #pragma unroll
                for (int mi = 0; mi < 4; mi++) {
                    #pragma unroll
                    for (int nj = 0; nj < 8; nj++) {
                        uint32_t b0 = bfr[cur][nj >> 1][(nj & 1) * 2 + 0];
                        uint32_t b1 = bfr[cur][nj >> 1][(nj & 1) * 2 + 1];
                        asm volatile(
                            "mma.sync.aligned.m16n8k16.row.col.f32.bf16.bf16.f32 "
                            "{%0,%1,%2,%3}, {%4,%5,%6,%7}, {%8,%9}, {%0,%1,%2,%3};"
                            : "+f"(acc[mi][nj][0]), "+f"(acc[mi][nj][1]),
                              "+f"(acc[mi][nj][2]), "+f"(acc[mi][nj][3])
                            : "r"(afr[cur][mi][0]), "r"(afr[cur][mi][1]),
                              "r"(afr[cur][mi][2]), "r"(afr[cur][mi][3]),
                              "r"(b0), "r"(b1));
                    }
                }
            }
            stage = (stage + 1 == NSTAGE) ? 0 : stage + 1;
        }

        // Epilogue: out = 7.5e-4 * (Z - 160*R[m] + 66*C[n] - 4096*66*160)
        const float s = 7.5e-4f;
        #pragma unroll
        for (int mi = 0; mi < 4; mi++) {
            int r0 = m0 + wm + mi * 16 + (lane >> 2);
            int r1 = r0 + 8;
            float bias0 = fmaf(-160.0f, g_R[r0], -43253760.0f);
            float bias1 = fmaf(-160.0f, g_R[r1], -43253760.0f);
            #pragma unroll
            for (int nj = 0; nj < 8; nj++) {
                int col = n0 + wn + nj * 8 + 2 * (lane & 3);
                float2 cv = *(const float2*)(g_C + col);
                float2 v0, v1;
                v0.x = (acc[mi][nj][0] + bias0 + 66.0f * cv.x) * s;
                v0.y = (acc[mi][nj][1] + bias0 + 66.0f * cv.y) * s;
                v1.x = (acc[mi][nj][2] + bias1 + 66.0f * cv.x) * s;
                v1.y = (acc[mi][nj][3] + bias1 + 66.0f * cv.y) * s;
                *(float2*)(out + (size_t)r0 * Nsz + col) = v0;
                *(float2*)(out + (size_t)r1 * Nsz + col) = v1;
            }
        }
        __syncthreads();   // all reads of this tile's smem done before next grab
    }
}

// ---------------- Launch ----------------
extern "C" void kernel_launch(void* const* d_in, const int* in_sizes, int n_in,
                              void* d_out, int out_size) {
    const float* x = (const float*)d_in[0];   // [M, K] fp32 (int-valued)
    const float* y = (const float*)d_in[1];   // [K, N] fp32 (int-valued)
    float* out = (float*)d_out;               // [M, N] fp32

    cudaFuncSetAttribute(gemm_kernel, cudaFuncAttributeMaxDynamicSharedMemorySize, SMEM_TOTAL);

    zero_c_kernel<<<16, 256>>>();
    prep_x_kernel<<<Msz, 256>>>(x);
    prep_y_kernel<<<dim3(Nsz / 32, Ksz / 32), dim3(32, 8)>>>(y);
    gemm_kernel<<<GRIDP, 256, SMEM_TOTAL>>>(out);
}

// round 11
// speedup vs baseline: 1.6120x; 1.6120x over previous
#include <cuda_runtime.h>
#include <cuda_bf16.h>
#include <cstdint>
#include <cstddef>

#define Msz 4096
#define Ksz 4096
#define Nsz 4096
#define TKC 64
#define NCHUNK (Ksz / TKC)   // 64

// Scratch (static device globals: allocation-free at runtime)
__device__ __nv_bfloat16 g_Xb[(size_t)Msz * Ksz];   // x as bf16, [M,K] row-major
__device__ __nv_bfloat16 g_Yt[(size_t)Nsz * Ksz];   // y^T as bf16, [N,K] row-major
__device__ float g_R[Msz];                          // rowsum of x
__device__ float g_C[Nsz];                          // colsum of y

__device__ __forceinline__ uint32_t smem_u32(const void* p) {
    uint32_t a;
    asm("{ .reg .u64 t; cvta.to.shared.u64 t, %1; cvt.u32.u64 %0, t; }" : "=r"(a) : "l"(p));
    return a;
}

#define SWZ(off) ((off) ^ (((off) >> 3) & 0x70))

// ---------------- Prep kernels ----------------
// One block per row of x: fp32 -> bf16 convert + rowsum. First 16 blocks also zero g_C
// (safe: prep_y runs in a later launch in the same stream).
__global__ void prep_x_kernel(const float* __restrict__ x) {
    int m = blockIdx.x;
    if (m < 16) {
        int base = m * 256;
        if (threadIdx.x < 256) g_C[base + threadIdx.x] = 0.0f;
    }
    const float4* xr = (const float4*)(x + (size_t)m * Ksz);
    uint2* dst = (uint2*)(g_Xb + (size_t)m * Ksz);
    float sum = 0.0f;
    for (int i = threadIdx.x; i < Ksz / 4; i += 256) {
        float4 v = xr[i];
        sum += (v.x + v.y) + (v.z + v.w);
        __nv_bfloat162 lo = __floats2bfloat162_rn(v.x, v.y);
        __nv_bfloat162 hi = __floats2bfloat162_rn(v.z, v.w);
        uint2 u;
        u.x = *reinterpret_cast<uint32_t*>(&lo);
        u.y = *reinterpret_cast<uint32_t*>(&hi);
        dst[i] = u;
    }
    #pragma unroll
    for (int o = 16; o; o >>= 1) sum += __shfl_xor_sync(0xFFFFFFFFu, sum, o);
    __shared__ float ws[8];
    if ((threadIdx.x & 31) == 0) ws[threadIdx.x >> 5] = sum;
    __syncthreads();
    if (threadIdx.x == 0) {
        float t = 0.0f;
        #pragma unroll
        for (int w = 0; w < 8; w++) t += ws[w];
        g_R[m] = t;
    }
}

// 32x32 tile transpose of y into Yt (bf16) + colsum via atomicAdd (partials exact ints)
__global__ void prep_y_kernel(const float* __restrict__ y) {
    __shared__ float tile[32][33];
    int n0 = blockIdx.x * 32, k0 = blockIdx.y * 32;
    int tx = threadIdx.x, ty = threadIdx.y;  // 32 x 8
    #pragma unroll
    for (int r = 0; r < 4; r++)
        tile[ty + r * 8][tx] = y[(size_t)(k0 + ty + r * 8) * Nsz + n0 + tx];
    __syncthreads();
    #pragma unroll
    for (int r = 0; r < 4; r++) {
        int row = ty + r * 8;
        g_Yt[(size_t)(n0 + row) * Ksz + k0 + tx] = __float2bfloat16(tile[tx][row]);
    }
    if (ty == 0) {
        float s = 0.0f;
        #pragma unroll
        for (int i = 0; i < 32; i++) s += tile[i][tx];
        atomicAdd(&g_C[n0 + tx], s);
    }
}

// ---------------- GEMM kernel (bf16 mma.sync, 3-stage cp.async, reordered) ----------------
// Dynamic SMEM: stage s at s*32K: A [0,16K), B [16K,32K). 3 stages = 96 KB.
#define ABYTES 16384
#define STAGEBYTES (2 * ABYTES)
#define NSTAGE 3
#define SMEM_TOTAL (NSTAGE * STAGEBYTES)   // 98304

__device__ __forceinline__ void load_chunk(uint32_t stage_base, int tid,
                                           int m0, int n0, int k0) {
    uint32_t abuf = stage_base;
    uint32_t bbuf = stage_base + ABYTES;
    const char* xb = (const char*)g_Xb;
    const char* yb = (const char*)g_Yt;
    #pragma unroll
    for (int e = 0; e < 4; e++) {
        int idx = tid + e * 256;
        int row = idx >> 3;      // 0..127
        int grp = idx & 7;       // 16B group (8 bf16) within 128B row
        uint32_t soff = SWZ((uint32_t)(row * 128 + grp * 16));
        size_t ea = ((size_t)(m0 + row) * Ksz + (size_t)(k0 + grp * 8)) * 2;
        asm volatile("cp.async.cg.shared.global [%0], [%1], 16;"
                     :: "r"(abuf + soff), "l"(xb + ea) : "memory");
        size_t eb = ((size_t)(n0 + row) * Ksz + (size_t)(k0 + grp * 8)) * 2;
        asm volatile("cp.async.cg.shared.global [%0], [%1], 16;"
                     :: "r"(bbuf + soff), "l"(yb + eb) : "memory");
    }
    asm volatile("cp.async.commit_group;" ::: "memory");
}

__device__ __forceinline__ void load_frags(uint32_t abase, uint32_t bbase, int ks,
                                           int a_row_lo, int a_kg_off,
                                           int b_row_lo, int b_kg_off,
                                           uint32_t afr[2][4], uint32_t bfr[4][4]) {
    #pragma unroll
    for (int mi = 0; mi < 2; mi++) {
        int row = a_row_lo + mi * 16;
        int kg = ks * 2 + a_kg_off;
        uint32_t addr = abase + SWZ((uint32_t)(row * 128 + kg * 16));
        asm volatile("ldmatrix.sync.aligned.m8n8.x4.shared.b16 {%0,%1,%2,%3}, [%4];"
                     : "=r"(afr[mi][0]), "=r"(afr[mi][1]),
                       "=r"(afr[mi][2]), "=r"(afr[mi][3])
                     : "r"(addr));
    }
    #pragma unroll
    for (int nj4 = 0; nj4 < 4; nj4++) {
        int row = b_row_lo + nj4 * 16;
        int kg = ks * 2 + b_kg_off;
        uint32_t addr = bbase + SWZ((uint32_t)(row * 128 + kg * 16));
        asm volatile("ldmatrix.sync.aligned.m8n8.x4.shared.b16 {%0,%1,%2,%3}, [%4];"
                     : "=r"(bfr[nj4][0]), "=r"(bfr[nj4][1]),
                       "=r"(bfr[nj4][2]), "=r"(bfr[nj4][3])
                     : "r"(addr));
    }
}

__global__ void __launch_bounds__(256, 2) gemm_kernel(float* __restrict__ out) {
    extern __shared__ char smem[];
    uint32_t sb = smem_u32(smem);
    int tid = threadIdx.x;
    int lane = tid & 31;
    int wid = tid >> 5;
    int m0 = blockIdx.y * 128;
    int n0 = blockIdx.x * 128;
    int wm = (wid >> 1) * 32;   // 4 warps in M
    int wn = (wid & 1) * 64;    // 2 warps in N

    float acc[2][8][4];
    #pragma unroll
    for (int i = 0; i < 2; i++)
        #pragma unroll
        for (int j = 0; j < 8; j++)
            #pragma unroll
            for (int q = 0; q < 4; q++) acc[i][j][q] = 0.0f;

    // ldmatrix address components (verified in round 2)
    int a_row_lo = wm + (lane & 15);                  // + mi*16
    int a_kg_off = (lane >> 4);                       // + ks*2
    int b_row_lo = wn + ((lane >> 4) << 3) + (lane & 7);   // + nj4*16
    int b_kg_off = ((lane >> 3) & 1);                      // + ks*2

    // Prologue: prefetch chunks 0 and 1
    load_chunk(sb + 0 * STAGEBYTES, tid, m0, n0, 0);
    load_chunk(sb + 1 * STAGEBYTES, tid, m0, n0, TKC);

    int stage = 0;
    for (int c = 0; c < NCHUNK; c++) {
        if (c + 1 < NCHUNK) {
            asm volatile("cp.async.wait_group 1;" ::: "memory");
        } else {
            asm volatile("cp.async.wait_group 0;" ::: "memory");
        }
        __syncthreads();   // chunk c visible; prior iteration's reads sealed

        uint32_t abase = sb + (uint32_t)stage * STAGEBYTES;
        uint32_t bbase = abase + ABYTES;

        // 1) Restart the tensor pipe ASAP: fragments for ks=0 first.
        uint32_t afr[2][2][4], bfr[2][4][4];
        load_frags(abase, bbase, 0, a_row_lo, a_kg_off, b_row_lo, b_kg_off,
                   afr[0], bfr[0]);

        // 2) Then issue next chunk's cp.asyncs (overlaps with MMA below).
        if (c + 2 < NCHUNK) {
            int ls = stage + 2;
            if (ls >= NSTAGE) ls -= NSTAGE;
            load_chunk(sb + (uint32_t)ls * STAGEBYTES, tid, m0, n0, (c + 2) * TKC);
        }

        // 3) ks loop with double-buffered fragments.
        #pragma unroll
        for (int ks = 0; ks < 4; ks++) {
            int cur = ks & 1;
            if (ks < 3)
                load_frags(abase, bbase, ks + 1, a_row_lo, a_kg_off,
                           b_row_lo, b_kg_off, afr[cur ^ 1], bfr[cur ^ 1]);
            #pragma unroll
            for (int mi = 0; mi < 2; mi++) {
                #pragma unroll
                for (int nj = 0; nj < 8; nj++) {
                    uint32_t b0 = bfr[cur][nj >> 1][(nj & 1) * 2 + 0];
                    uint32_t b1 = bfr[cur][nj >> 1][(nj & 1) * 2 + 1];
                    asm volatile(
                        "mma.sync.aligned.m16n8k16.row.col.f32.bf16.bf16.f32 "
                        "{%0,%1,%2,%3}, {%4,%5,%6,%7}, {%8,%9}, {%0,%1,%2,%3};"
                        : "+f"(acc[mi][nj][0]), "+f"(acc[mi][nj][1]),
                          "+f"(acc[mi][nj][2]), "+f"(acc[mi][nj][3])
                        : "r"(afr[cur][mi][0]), "r"(afr[cur][mi][1]),
                          "r"(afr[cur][mi][2]), "r"(afr[cur][mi][3]),
                          "r"(b0), "r"(b1));
                }
            }
        }
        stage = (stage + 1 == NSTAGE) ? 0 : stage + 1;
    }

    // Epilogue: out = 7.5e-4 * (Z - 160*R[m] + 66*C[n] - 4096*66*160)
    const float s = 7.5e-4f;
    #pragma unroll
    for (int mi = 0; mi < 2; mi++) {
        int r0 = m0 + wm + mi * 16 + (lane >> 2);
        int r1 = r0 + 8;
        float bias0 = fmaf(-160.0f, g_R[r0], -43253760.0f);
        float bias1 = fmaf(-160.0f, g_R[r1], -43253760.0f);
        #pragma unroll
        for (int nj = 0; nj < 8; nj++) {
            int col = n0 + wn + nj * 8 + 2 * (lane & 3);
            float2 cv = *(const float2*)(g_C + col);
            float2 v0, v1;
            v0.x = (acc[mi][nj][0] + bias0 + 66.0f * cv.x) * s;
            v0.y = (acc[mi][nj][1] + bias0 + 66.0f * cv.y) * s;
            v1.x = (acc[mi][nj][2] + bias1 + 66.0f * cv.x) * s;
            v1.y = (acc[mi][nj][3] + bias1 + 66.0f * cv.y) * s;
            *(float2*)(out + (size_t)r0 * Nsz + col) = v0;
            *(float2*)(out + (size_t)r1 * Nsz + col) = v1;
        }
    }
}

// ---------------- Launch ----------------
extern "C" void kernel_launch(void* const* d_in, const int* in_sizes, int n_in,
                              void* d_out, int out_size) {
    const float* x = (const float*)d_in[0];   // [M, K] fp32 (int-valued)
    const float* y = (const float*)d_in[1];   // [K, N] fp32 (int-valued)
    float* out = (float*)d_out;               // [M, N] fp32

    cudaFuncSetAttribute(gemm_kernel, cudaFuncAttributeMaxDynamicSharedMemorySize, SMEM_TOTAL);

    prep_x_kernel<<<Msz, 256>>>(x);
    prep_y_kernel<<<dim3(Nsz / 32, Ksz / 32), dim3(32, 8)>>>(y);
    gemm_kernel<<<dim3(Nsz / 128, Msz / 128), 256, SMEM_TOTAL>>>(out);
}

// round 12
// speedup vs baseline: 1.7224x; 1.0685x over previous
#include <cuda_runtime.h>
#include <cuda_bf16.h>
#include <cstdint>
#include <cstddef>

#define Msz 4096
#define Ksz 4096
#define Nsz 4096
#define TKC 64
#define NCHUNK (Ksz / TKC)   // 64

// Scratch (static device globals: allocation-free at runtime)
__device__ __nv_bfloat16 g_Xb[(size_t)Msz * Ksz];   // x as bf16, [M,K] row-major
__device__ __nv_bfloat16 g_Yt[(size_t)Nsz * Ksz];   // y^T as bf16, [N,K] row-major
__device__ float g_R[Msz];                          // rowsum of x
__device__ float g_C[Nsz];                          // colsum of y

__device__ __forceinline__ uint32_t smem_u32(const void* p) {
    uint32_t a;
    asm("{ .reg .u64 t; cvta.to.shared.u64 t, %1; cvt.u32.u64 %0, t; }" : "=r"(a) : "l"(p));
    return a;
}

#define SWZ(off) ((off) ^ (((off) >> 3) & 0x70))

// ---------------- Prep kernels ----------------
// One block per row of x: fp32 -> bf16 convert + rowsum. First 16 blocks also zero g_C
// (safe: prep_y runs in a later launch in the same stream).
__global__ void prep_x_kernel(const float* __restrict__ x) {
    int m = blockIdx.x;
    if (m < 16) {
        int base = m * 256;
        g_C[base + threadIdx.x] = 0.0f;
    }
    const float4* xr = (const float4*)(x + (size_t)m * Ksz);
    uint2* dst = (uint2*)(g_Xb + (size_t)m * Ksz);
    float sum = 0.0f;
    for (int i = threadIdx.x; i < Ksz / 4; i += 256) {
        float4 v = xr[i];
        sum += (v.x + v.y) + (v.z + v.w);
        __nv_bfloat162 lo = __floats2bfloat162_rn(v.x, v.y);
        __nv_bfloat162 hi = __floats2bfloat162_rn(v.z, v.w);
        uint2 u;
        u.x = *reinterpret_cast<uint32_t*>(&lo);
        u.y = *reinterpret_cast<uint32_t*>(&hi);
        dst[i] = u;
    }
    #pragma unroll
    for (int o = 16; o; o >>= 1) sum += __shfl_xor_sync(0xFFFFFFFFu, sum, o);
    __shared__ float ws[8];
    if ((threadIdx.x & 31) == 0) ws[threadIdx.x >> 5] = sum;
    __syncthreads();
    if (threadIdx.x == 0) {
        float t = 0.0f;
        #pragma unroll
        for (int w = 0; w < 8; w++) t += ws[w];
        g_R[m] = t;
    }
}

// 32x32 tile transpose of y into Yt (bf16) + colsum via atomicAdd (partials exact ints)
__global__ void prep_y_kernel(const float* __restrict__ y) {
    __shared__ float tile[32][33];
    int n0 = blockIdx.x * 32, k0 = blockIdx.y * 32;
    int tx = threadIdx.x, ty = threadIdx.y;  // 32 x 8
    #pragma unroll
    for (int r = 0; r < 4; r++)
        tile[ty + r * 8][tx] = y[(size_t)(k0 + ty + r * 8) * Nsz + n0 + tx];
    __syncthreads();
    #pragma unroll
    for (int r = 0; r < 4; r++) {
        int row = ty + r * 8;
        g_Yt[(size_t)(n0 + row) * Ksz + k0 + tx] = __float2bfloat16(tile[tx][row]);
    }
    if (ty == 0) {
        float s = 0.0f;
        #pragma unroll
        for (int i = 0; i < 32; i++) s += tile[i][tx];
        atomicAdd(&g_C[n0 + tx], s);
    }
}

// ---------------- GEMM kernel (bf16 mma.sync, 3-stage cp.async) ----------------
// Dynamic SMEM: stage s at s*32K: A [0,16K), B [16K,32K). 3 stages = 96 KB.
#define ABYTES 16384
#define STAGEBYTES (2 * ABYTES)
#define NSTAGE 3
#define SMEM_TOTAL (NSTAGE * STAGEBYTES)   // 98304

__device__ __forceinline__ void load_chunk(uint32_t stage_base, int tid,
                                           int m0, int n0, int k0) {
    uint32_t abuf = stage_base;
    uint32_t bbuf = stage_base + ABYTES;
    const char* xb = (const char*)g_Xb;
    const char* yb = (const char*)g_Yt;
    #pragma unroll
    for (int e = 0; e < 4; e++) {
        int idx = tid + e * 256;
        int row = idx >> 3;      // 0..127
        int grp = idx & 7;       // 16B group (8 bf16) within 128B row
        uint32_t soff = SWZ((uint32_t)(row * 128 + grp * 16));
        size_t ea = ((size_t)(m0 + row) * Ksz + (size_t)(k0 + grp * 8)) * 2;
        asm volatile("cp.async.cg.shared.global [%0], [%1], 16;"
                     :: "r"(abuf + soff), "l"(xb + ea) : "memory");
        size_t eb = ((size_t)(n0 + row) * Ksz + (size_t)(k0 + grp * 8)) * 2;
        asm volatile("cp.async.cg.shared.global [%0], [%1], 16;"
                     :: "r"(bbuf + soff), "l"(yb + eb) : "memory");
    }
    asm volatile("cp.async.commit_group;" ::: "memory");
}

__device__ __forceinline__ void load_frags(uint32_t abase, uint32_t bbase, int ks,
                                           int a_row_lo, int a_kg_off,
                                           int b_row_lo, int b_kg_off,
                                           uint32_t afr[2][4], uint32_t bfr[4][4]) {
    #pragma unroll
    for (int mi = 0; mi < 2; mi++) {
        int row = a_row_lo + mi * 16;
        int kg = ks * 2 + a_kg_off;
        uint32_t addr = abase + SWZ((uint32_t)(row * 128 + kg * 16));
        asm volatile("ldmatrix.sync.aligned.m8n8.x4.shared.b16 {%0,%1,%2,%3}, [%4];"
                     : "=r"(afr[mi][0]), "=r"(afr[mi][1]),
                       "=r"(afr[mi][2]), "=r"(afr[mi][3])
                     : "r"(addr));
    }
    #pragma unroll
    for (int nj4 = 0; nj4 < 4; nj4++) {
        int row = b_row_lo + nj4 * 16;
        int kg = ks * 2 + b_kg_off;
        uint32_t addr = bbase + SWZ((uint32_t)(row * 128 + kg * 16));
        asm volatile("ldmatrix.sync.aligned.m8n8.x4.shared.b16 {%0,%1,%2,%3}, [%4];"
                     : "=r"(bfr[nj4][0]), "=r"(bfr[nj4][1]),
                       "=r"(bfr[nj4][2]), "=r"(bfr[nj4][3])
                     : "r"(addr));
    }
}

__global__ void __launch_bounds__(256, 2) gemm_kernel(float* __restrict__ out) {
    extern __shared__ char smem[];
    uint32_t sb = smem_u32(smem);
    int tid = threadIdx.x;
    int lane = tid & 31;
    int wid = tid >> 5;
    int m0 = blockIdx.y * 128;
    int n0 = blockIdx.x * 128;
    int wm = (wid >> 1) * 32;   // 4 warps in M
    int wn = (wid & 1) * 64;    // 2 warps in N

    float acc[2][8][4];
    #pragma unroll
    for (int i = 0; i < 2; i++)
        #pragma unroll
        for (int j = 0; j < 8; j++)
            #pragma unroll
            for (int q = 0; q < 4; q++) acc[i][j][q] = 0.0f;

    // ldmatrix address components (verified in round 2)
    int a_row_lo = wm + (lane & 15);                  // + mi*16
    int a_kg_off = (lane >> 4);                       // + ks*2
    int b_row_lo = wn + ((lane >> 4) << 3) + (lane & 7);   // + nj4*16
    int b_kg_off = ((lane >> 3) & 1);                      // + ks*2

    // Prologue: prefetch chunks 0 and 1
    load_chunk(sb + 0 * STAGEBYTES, tid, m0, n0, 0);
    load_chunk(sb + 1 * STAGEBYTES, tid, m0, n0, TKC);

    int stage = 0;
    for (int c = 0; c < NCHUNK; c++) {
        if (c + 1 < NCHUNK) {
            asm volatile("cp.async.wait_group 1;" ::: "memory");
        } else {
            asm volatile("cp.async.wait_group 0;" ::: "memory");
        }
        __syncthreads();   // chunk c visible; prior iteration's reads sealed

        uint32_t abase = sb + (uint32_t)stage * STAGEBYTES;
        uint32_t bbase = abase + ABYTES;

        // 1) Restart the tensor path ASAP: ks=0 fragments BEFORE the LSU burst.
        uint32_t afr[2][4], bfr[4][4];
        load_frags(abase, bbase, 0, a_row_lo, a_kg_off, b_row_lo, b_kg_off, afr, bfr);

        // 2) Next chunk's cp.asyncs issue while ks=0 LDSMs/MMAs execute.
        if (c + 2 < NCHUNK) {
            int ls = stage + 2;
            if (ls >= NSTAGE) ls -= NSTAGE;
            load_chunk(sb + (uint32_t)ls * STAGEBYTES, tid, m0, n0, (c + 2) * TKC);
        }

        // 3) ks loop: single fragment set, rotated load-after-use (no extra regs).
        #pragma unroll
        for (int ks = 0; ks < 4; ks++) {
            #pragma unroll
            for (int mi = 0; mi < 2; mi++) {
                #pragma unroll
                for (int nj = 0; nj < 8; nj++) {
                    uint32_t b0 = bfr[nj >> 1][(nj & 1) * 2 + 0];
                    uint32_t b1 = bfr[nj >> 1][(nj & 1) * 2 + 1];
                    asm volatile(
                        "mma.sync.aligned.m16n8k16.row.col.f32.bf16.bf16.f32 "
                        "{%0,%1,%2,%3}, {%4,%5,%6,%7}, {%8,%9}, {%0,%1,%2,%3};"
                        : "+f"(acc[mi][nj][0]), "+f"(acc[mi][nj][1]),
                          "+f"(acc[mi][nj][2]), "+f"(acc[mi][nj][3])
                        : "r"(afr[mi][0]), "r"(afr[mi][1]),
                          "r"(afr[mi][2]), "r"(afr[mi][3]),
                          "r"(b0), "r"(b1));
                }
            }
            if (ks < 3)
                load_frags(abase, bbase, ks + 1, a_row_lo, a_kg_off,
                           b_row_lo, b_kg_off, afr, bfr);
        }
        stage = (stage + 1 == NSTAGE) ? 0 : stage + 1;
    }

    // Epilogue: out = 7.5e-4 * (Z - 160*R[m] + 66*C[n] - 4096*66*160)
    const float s = 7.5e-4f;
    #pragma unroll
    for (int mi = 0; mi < 2; mi++) {
        int r0 = m0 + wm + mi * 16 + (lane >> 2);
        int r1 = r0 + 8;
        float bias0 = fmaf(-160.0f, g_R[r0], -43253760.0f);
        float bias1 = fmaf(-160.0f, g_R[r1], -43253760.0f);
        #pragma unroll
        for (int nj = 0; nj < 8; nj++) {
            int col = n0 + wn + nj * 8 + 2 * (lane & 3);
            float2 cv = *(const float2*)(g_C + col);
            float2 v0, v1;
            v0.x = (acc[mi][nj][0] + bias0 + 66.0f * cv.x) * s;
            v0.y = (acc[mi][nj][1] + bias0 + 66.0f * cv.y) * s;
            v1.x = (acc[mi][nj][2] + bias1 + 66.0f * cv.x) * s;
            v1.y = (acc[mi][nj][3] + bias1 + 66.0f * cv.y) * s;
            *(float2*)(out + (size_t)r0 * Nsz + col) = v0;
            *(float2*)(out + (size_t)r1 * Nsz + col) = v1;
        }
    }
}

// ---------------- Launch ----------------
extern "C" void kernel_launch(void* const* d_in, const int* in_sizes, int n_in,
                              void* d_out, int out_size) {
    const float* x = (const float*)d_in[0];   // [M, K] fp32 (int-valued)
    const float* y = (const float*)d_in[1];   // [K, N] fp32 (int-valued)
    float* out = (float*)d_out;               // [M, N] fp32

    cudaFuncSetAttribute(gemm_kernel, cudaFuncAttributeMaxDynamicSharedMemorySize, SMEM_TOTAL);

    prep_x_kernel<<<Msz, 256>>>(x);
    prep_y_kernel<<<dim3(Nsz / 32, Ksz / 32), dim3(32, 8)>>>(y);
    gemm_kernel<<<dim3(Nsz / 128, Msz / 128), 256, SMEM_TOTAL>>>(out);
}